// round 11
// baseline (speedup 1.0000x reference)
#include <cuda_runtime.h>
#include <cuda_bf16.h>
#include <stdint.h>

#define NTOK 8192
#define DIM  1024
#define DK   128
#define DV   128

// ---------------- device globals (allocation-free scratch) ----------------
__device__ float g_v[NTOK * DV];
__device__ __align__(256) __nv_bfloat16 g_qkh[NTOK * DK];   // qk bf16 row-major
__device__ __align__(256) float g_ss[NTOK];                 // ||qk_i||^2 fp32
__device__ __align__(256) float g_O[2][NTOK * DV];          // split-KV numerators
__device__ __align__(256) float g_l[2][NTOK];               // split-KV denominators

// ---------------- helpers ----------------
__device__ __forceinline__ uint32_t smem_to_u32(const void* p) {
    uint32_t a;
    asm("{ .reg .u64 t; cvta.to.shared.u64 t, %1; cvt.u32.u64 %0, t; }" : "=r"(a) : "l"(p));
    return a;
}
__device__ __forceinline__ void cp16(uint32_t dst, const void* src) {
    asm volatile("cp.async.cg.shared.global [%0], [%1], 16;" :: "r"(dst), "l"(src) : "memory");
}
#define CP_COMMIT() asm volatile("cp.async.commit_group;" ::: "memory")
#define CP_WAIT0()  asm volatile("cp.async.wait_group 0;" ::: "memory")

__device__ __forceinline__ uint32_t bf2_to_u32(__nv_bfloat162 v) {
    uint32_t u; *(__nv_bfloat162*)&u = v; return u;
}

#define LDSM_X4(r0, r1, r2, r3, a) \
    asm volatile("ldmatrix.sync.aligned.m8n8.x4.shared.b16 {%0,%1,%2,%3}, [%4];" \
                 : "=r"(r0), "=r"(r1), "=r"(r2), "=r"(r3) : "r"(a))
#define LDSM_X2_T(r0, r1, a) \
    asm volatile("ldmatrix.sync.aligned.m8n8.x2.trans.shared.b16 {%0,%1}, [%2];" \
                 : "=r"(r0), "=r"(r1) : "r"(a))
// D(f32 4) += A(bf16 16x16) * B(bf16 16x8 col)
#define MMA16816(d, a, b0, b1) \
    asm volatile("mma.sync.aligned.m16n8k16.row.col.f32.bf16.bf16.f32 " \
                 "{%0,%1,%2,%3}, {%4,%5,%6,%7}, {%8,%9}, {%0,%1,%2,%3};" \
                 : "+f"((d)[0]), "+f"((d)[1]), "+f"((d)[2]), "+f"((d)[3]) \
                 : "r"((a)[0]), "r"((a)[1]), "r"((a)[2]), "r"((a)[3]), "r"(b0), "r"(b1))

// ============================================================================
// proj (HMMA, bf16 hi/lo 3-product split) — proven, unchanged
// ============================================================================
#define PJ_ROWB 144
#define PJ_AH 0
#define PJ_AL 18432
#define PJ_BH 36864
#define PJ_BL 55296
#define PJ_SA 73728
#define PJ_SB 106496
#define PJ_SMEM 139264

__global__ __launch_bounds__(256, 1)
void proj_hmma_kernel(const float* __restrict__ x,
                      const float* __restrict__ Wqk, const float* __restrict__ bqk,
                      const float* __restrict__ Wv,  const float* __restrict__ bv) {
    extern __shared__ char smem[];
    const uint32_t sb = smem_to_u32(smem);
    const int tid = threadIdx.x, wid = tid >> 5, lane = tid & 31;
    const int row0 = blockIdx.x * 128;
    const int type = blockIdx.y;
    const float* W = type ? Wv : Wqk;
    const float* bias = type ? bv : bqk;

    const int rA = ((lane >> 3) & 1) * 8 + (lane & 7);
    const int kA = (lane >> 4) & 1;
    const int rB = ((lane >> 4) & 1) * 8 + (lane & 7);
    const int kB = (lane >> 3) & 1;

    float acc[16][4];
#pragma unroll
    for (int nt = 0; nt < 16; nt++)
#pragma unroll
        for (int q = 0; q < 4; q++) acc[nt][q] = 0.f;

#pragma unroll
    for (int it = 0; it < 8; it++) {
        int idx = it * 256 + tid;
        int r = idx >> 4, kq = (idx & 15) * 4;
        cp16(sb + PJ_SA + r * 256 + kq * 4, &x[(size_t)(row0 + r) * DIM + kq]);
        cp16(sb + PJ_SB + r * 256 + kq * 4, &W[(size_t)r * DIM + kq]);
    }
    CP_COMMIT();

    for (int c = 0; c < 16; c++) {
        CP_WAIT0();
        __syncthreads();

#pragma unroll
        for (int it = 0; it < 8; it++) {
            int idx = it * 256 + tid;
            int r = idx >> 4, kq = (idx & 15) * 4;
            float4 fa = *(const float4*)(smem + PJ_SA + r * 256 + kq * 4);
            float4 fb = *(const float4*)(smem + PJ_SB + r * 256 + kq * 4);
            __nv_bfloat162 ah0 = __floats2bfloat162_rn(fa.x, fa.y);
            __nv_bfloat162 ah1 = __floats2bfloat162_rn(fa.z, fa.w);
            __nv_bfloat162 al0 = __floats2bfloat162_rn(fa.x - __bfloat162float(ah0.x),
                                                       fa.y - __bfloat162float(ah0.y));
            __nv_bfloat162 al1 = __floats2bfloat162_rn(fa.z - __bfloat162float(ah1.x),
                                                       fa.w - __bfloat162float(ah1.y));
            __nv_bfloat162 bh0 = __floats2bfloat162_rn(fb.x, fb.y);
            __nv_bfloat162 bh1 = __floats2bfloat162_rn(fb.z, fb.w);
            __nv_bfloat162 bl0 = __floats2bfloat162_rn(fb.x - __bfloat162float(bh0.x),
                                                       fb.y - __bfloat162float(bh0.y));
            __nv_bfloat162 bl1 = __floats2bfloat162_rn(fb.z - __bfloat162float(bh1.x),
                                                       fb.w - __bfloat162float(bh1.y));
            uint2 u;
            u.x = bf2_to_u32(ah0); u.y = bf2_to_u32(ah1);
            *(uint2*)(smem + PJ_AH + r * PJ_ROWB + kq * 2) = u;
            u.x = bf2_to_u32(al0); u.y = bf2_to_u32(al1);
            *(uint2*)(smem + PJ_AL + r * PJ_ROWB + kq * 2) = u;
            u.x = bf2_to_u32(bh0); u.y = bf2_to_u32(bh1);
            *(uint2*)(smem + PJ_BH + r * PJ_ROWB + kq * 2) = u;
            u.x = bf2_to_u32(bl0); u.y = bf2_to_u32(bl1);
            *(uint2*)(smem + PJ_BL + r * PJ_ROWB + kq * 2) = u;
        }
        __syncthreads();

        if (c + 1 < 16) {
            const int kk = (c + 1) * 64;
#pragma unroll
            for (int it = 0; it < 8; it++) {
                int idx = it * 256 + tid;
                int r = idx >> 4, kq = (idx & 15) * 4;
                cp16(sb + PJ_SA + r * 256 + kq * 4, &x[(size_t)(row0 + r) * DIM + kk + kq]);
                cp16(sb + PJ_SB + r * 256 + kq * 4, &W[(size_t)r * DIM + kk + kq]);
            }
            CP_COMMIT();
        }

        uint32_t ah[4][4], al[4][4];
        const uint32_t arh = sb + PJ_AH + (uint32_t)(wid * 16 + rA) * PJ_ROWB;
        const uint32_t arl = sb + PJ_AL + (uint32_t)(wid * 16 + rA) * PJ_ROWB;
#pragma unroll
        for (int s = 0; s < 4; s++) {
            LDSM_X4(ah[s][0], ah[s][1], ah[s][2], ah[s][3], arh + (s * 16 + kA * 8) * 2);
            LDSM_X4(al[s][0], al[s][1], al[s][2], al[s][3], arl + (s * 16 + kA * 8) * 2);
        }

#pragma unroll
        for (int s = 0; s < 4; s++) {
#pragma unroll
            for (int ng = 0; ng < 8; ng++) {
                uint32_t bh0, bh1, bh2, bh3, bl0, bl1, bl2, bl3;
                const uint32_t boff = (uint32_t)(ng * 16 + rB) * PJ_ROWB + (s * 16 + kB * 8) * 2;
                LDSM_X4(bh0, bh1, bh2, bh3, sb + PJ_BH + boff);
                LDSM_X4(bl0, bl1, bl2, bl3, sb + PJ_BL + boff);
                MMA16816(acc[2 * ng],     ah[s], bh0, bh1);
                MMA16816(acc[2 * ng + 1], ah[s], bh2, bh3);
                MMA16816(acc[2 * ng],     ah[s], bl0, bl1);
                MMA16816(acc[2 * ng + 1], ah[s], bl2, bl3);
                MMA16816(acc[2 * ng],     al[s], bh0, bh1);
                MMA16816(acc[2 * ng + 1], al[s], bh2, bh3);
            }
        }
    }

    const int rl = row0 + wid * 16 + (lane >> 2);
    const int rh = rl + 8;
    if (type == 0) {
        float ss0 = 0.f, ss1 = 0.f;
#pragma unroll
        for (int nt = 0; nt < 16; nt++) {
            const int col = nt * 8 + 2 * (lane & 3);
            float2 bb = *(const float2*)&bias[col];
            float c0 = acc[nt][0] + bb.x, c1 = acc[nt][1] + bb.y;
            float c2 = acc[nt][2] + bb.x, c3 = acc[nt][3] + bb.y;
            ss0 += c0 * c0 + c1 * c1;
            ss1 += c2 * c2 + c3 * c3;
            *(uint32_t*)&g_qkh[(size_t)rl * DK + col] = bf2_to_u32(__floats2bfloat162_rn(c0, c1));
            *(uint32_t*)&g_qkh[(size_t)rh * DK + col] = bf2_to_u32(__floats2bfloat162_rn(c2, c3));
        }
        ss0 += __shfl_xor_sync(0xffffffffu, ss0, 1);
        ss0 += __shfl_xor_sync(0xffffffffu, ss0, 2);
        ss1 += __shfl_xor_sync(0xffffffffu, ss1, 1);
        ss1 += __shfl_xor_sync(0xffffffffu, ss1, 2);
        if ((lane & 3) == 0) { g_ss[rl] = ss0; g_ss[rh] = ss1; }
    } else {
#pragma unroll
        for (int nt = 0; nt < 16; nt++) {
            const int col = nt * 8 + 2 * (lane & 3);
            float2 bb = *(const float2*)&bias[col];
            float2 v0; v0.x = acc[nt][0] + bb.x; v0.y = acc[nt][1] + bb.y;
            float2 v1; v1.x = acc[nt][2] + bb.x; v1.y = acc[nt][3] + bb.y;
            *(float2*)&g_v[(size_t)rl * DV + col] = v0;
            *(float2*)&g_v[(size_t)rh * DV + col] = v1;
        }
    }
}

// ============================================================================
// attention: BM=128, 256 thr, split-KV x2. Round-11: 2-D warp tiling of the
// S screen (warp = 32 rows x 64 keys) halves smem B traffic; row-max via smem
// exchange. Active tiles: exp same S values -> P smem buffer -> PV tiled
// (32 rows x 64 dv per warp). Margin 14 (proven R10).
// ============================================================================
#define ROWB 272
#define AT_K0 0
#define AT_K1 34816
#define AT_P  69632
#define AT_VH 104448
#define AT_VL 139264
#define AT_RMAX 174080               // float[2][128]
#define AT_STHR (AT_RMAX + 1024)     // float[128]
#define AT_LRED (AT_STHR + 512)      // float[2][128]
#define AT_GARR (AT_LRED + 1024)     // int[4]
#define ATT_SMEM (AT_GARR + 16)

__global__ __launch_bounds__(256, 1)
void attn_kernel() {
    extern __shared__ char smem[];
    const uint32_t sb = smem_to_u32(smem);
    float* rmax = (float*)(smem + AT_RMAX);   // [hf*128 + r]
    float* sthr = (float*)(smem + AT_STHR);
    float* lred = (float*)(smem + AT_LRED);
    int*   garr = (int*)(smem + AT_GARR);
    const int tid = threadIdx.x, wid = tid >> 5, lane = tid & 31;
    const int g = wid & 3, hf = wid >> 2;
    const int row0 = blockIdx.x * 128;
    const int h = blockIdx.y;
    const int j0base = h * 4096;

    const int rA = ((lane >> 3) & 1) * 8 + (lane & 7);
    const int kA = (lane >> 4) & 1;
    const int rB = ((lane >> 4) & 1) * 8 + (lane & 7);
    const int kB = (lane >> 3) & 1;
    const int qr = lane >> 2, c2 = lane & 3;

    int R[4];
    R[0] = 32 * g + qr; R[1] = R[0] + 8; R[2] = R[0] + 16; R[3] = R[0] + 24;
    float m4[4];
#pragma unroll
    for (int j = 0; j < 4; j++) m4[j] = g_ss[row0 + R[j]];

    // stage Q (into P buffer) and K tile 0; init thresholds
#pragma unroll
    for (int it = 0; it < 8; it++) {
        int c = it * 256 + tid;
        int r = c >> 4, cc = (c & 15) * 8;
        cp16(sb + AT_P  + r * ROWB + cc * 2, &g_qkh[(size_t)(row0 + r) * DK + cc]);
        cp16(sb + AT_K0 + r * ROWB + cc * 2, &g_qkh[(size_t)(j0base + r) * DK + cc]);
    }
    if (tid < 128) sthr[tid] = g_ss[row0 + tid] - 14.f;
    CP_COMMIT(); CP_WAIT0();
    __syncthreads();

    // Q A-frags for this warp's 32 rows (held in regs for all tiles)
    uint32_t qa2[2][8][4];
#pragma unroll
    for (int r16 = 0; r16 < 2; r16++) {
        const uint32_t qrow = sb + AT_P + (uint32_t)(32 * g + 16 * r16 + rA) * ROWB;
#pragma unroll
        for (int s = 0; s < 8; s++)
            LDSM_X4(qa2[r16][s][0], qa2[r16][s][1], qa2[r16][s][2], qa2[r16][s][3],
                    qrow + (s * 16 + kA * 8) * 2);
    }
    __syncthreads();   // Q reads done before P buffer reuse

    float oa[16][4];   // [r16*8+nv], rows 32g+16r16+qr(+8), dv 64hf+8nv+2c2(+1)
#pragma unroll
    for (int f = 0; f < 16; f++)
#pragma unroll
        for (int q = 0; q < 4; q++) oa[f][q] = 0.f;
    float l4[4] = {0.f, 0.f, 0.f, 0.f};

    for (int t = 0; t < 32; t++) {
        if (t > 0) CP_WAIT0();
        __syncthreads();
        if (tid < 4) garr[tid] = 0;

        if (t + 1 < 32) {
            const uint32_t nb = sb + ((t & 1) ? AT_K0 : AT_K1);
            const int j1 = j0base + (t + 1) * 128;
#pragma unroll
            for (int it = 0; it < 8; it++) {
                int c = it * 256 + tid;
                int r = c >> 4, cc = (c & 15) * 8;
                cp16(nb + r * ROWB + cc * 2, &g_qkh[(size_t)(j1 + r) * DK + cc]);
            }
            CP_COMMIT();
        }

        // S screen: this warp = rows 32g..+31 x keys 64hf..+63
        const uint32_t kb = sb + ((t & 1) ? AT_K1 : AT_K0);
        float sa[16][4];   // [np*4 + r16*2 + j]
#pragma unroll
        for (int f = 0; f < 16; f++)
#pragma unroll
            for (int q = 0; q < 4; q++) sa[f][q] = 0.f;
#pragma unroll
        for (int s = 0; s < 8; s++) {
            const uint32_t kcol = kb + (uint32_t)((s * 16 + kB * 8) * 2);
#pragma unroll
            for (int np = 0; np < 4; np++) {
                uint32_t b0, b1, b2, b3;
                LDSM_X4(b0, b1, b2, b3, kcol + (uint32_t)(64 * hf + np * 16 + rB) * ROWB);
                MMA16816(sa[np * 4 + 0], qa2[0][s], b0, b1);
                MMA16816(sa[np * 4 + 1], qa2[0][s], b2, b3);
                MMA16816(sa[np * 4 + 2], qa2[1][s], b0, b1);
                MMA16816(sa[np * 4 + 3], qa2[1][s], b2, b3);
            }
        }

        // row maxes over this warp's 64 keys
        float mx[4] = {-3.0e38f, -3.0e38f, -3.0e38f, -3.0e38f};
#pragma unroll
        for (int np = 0; np < 4; np++)
#pragma unroll
            for (int j = 0; j < 2; j++) {
                const int f0 = np * 4 + j, f1 = np * 4 + 2 + j;
                mx[0] = fmaxf(mx[0], fmaxf(sa[f0][0], sa[f0][1]));
                mx[1] = fmaxf(mx[1], fmaxf(sa[f0][2], sa[f0][3]));
                mx[2] = fmaxf(mx[2], fmaxf(sa[f1][0], sa[f1][1]));
                mx[3] = fmaxf(mx[3], fmaxf(sa[f1][2], sa[f1][3]));
            }
#pragma unroll
        for (int j = 0; j < 4; j++) {
            mx[j] = fmaxf(mx[j], __shfl_xor_sync(0xffffffffu, mx[j], 1));
            mx[j] = fmaxf(mx[j], __shfl_xor_sync(0xffffffffu, mx[j], 2));
        }
        if (c2 == 0) {
#pragma unroll
            for (int j = 0; j < 4; j++) rmax[hf * 128 + R[j]] = mx[j];
        }
        __syncthreads();
        if (tid < 128) {
            float cm = fmaxf(rmax[tid], rmax[128 + tid]);
            if (cm >= sthr[tid]) garr[tid >> 5] = 1;
        }
        __syncthreads();
        const int cact = garr[0] | garr[1] | garr[2] | garr[3];

        if (cact) {
            const int j0 = j0base + t * 128;
            // V tile hi/lo (all threads)
#pragma unroll
            for (int it = 0; it < 16; it++) {
                int idx = it * 256 + tid;
                int r = idx >> 5, cq = (idx & 31) * 4;
                float4 f = *(const float4*)&g_v[(size_t)(j0 + r) * DV + cq];
                __nv_bfloat162 h0 = __floats2bfloat162_rn(f.x, f.y);
                __nv_bfloat162 h1 = __floats2bfloat162_rn(f.z, f.w);
                __nv_bfloat162 e0 = __floats2bfloat162_rn(f.x - __bfloat162float(h0.x),
                                                          f.y - __bfloat162float(h0.y));
                __nv_bfloat162 e1 = __floats2bfloat162_rn(f.z - __bfloat162float(h1.x),
                                                          f.w - __bfloat162float(h1.y));
                uint2 uh; uh.x = bf2_to_u32(h0); uh.y = bf2_to_u32(h1);
                uint2 ul; ul.x = bf2_to_u32(e0); ul.y = bf2_to_u32(e1);
                *(uint2*)(smem + AT_VH + r * ROWB + cq * 2) = uh;
                *(uint2*)(smem + AT_VL + r * ROWB + cq * 2) = ul;
            }

            const int ga = garr[g];
            if (ga) {
                bool act4[4];
#pragma unroll
                for (int j = 0; j < 4; j++)
                    act4[j] = fmaxf(rmax[R[j]], rmax[128 + R[j]]) >= (m4[j] - 14.f);
                // exp -> P (bf16) in smem; l from the SAME rounded p
#pragma unroll
                for (int np = 0; np < 4; np++)
#pragma unroll
                    for (int r16 = 0; r16 < 2; r16++)
#pragma unroll
                        for (int j = 0; j < 2; j++) {
                            const int f = np * 4 + r16 * 2 + j;
                            const int col = 64 * hf + 16 * np + 2 * c2 + 8 * j;
                            float e0 = act4[2 * r16] ? __expf(sa[f][0] - m4[2 * r16]) : 0.f;
                            float e1 = act4[2 * r16] ? __expf(sa[f][1] - m4[2 * r16]) : 0.f;
                            __nv_bfloat162 b = __floats2bfloat162_rn(e0, e1);
                            *(uint32_t*)(smem + AT_P + R[2 * r16] * ROWB + col * 2) = bf2_to_u32(b);
                            l4[2 * r16] += __bfloat162float(b.x) + __bfloat162float(b.y);
                            float e2 = act4[2 * r16 + 1] ? __expf(sa[f][2] - m4[2 * r16 + 1]) : 0.f;
                            float e3 = act4[2 * r16 + 1] ? __expf(sa[f][3] - m4[2 * r16 + 1]) : 0.f;
                            b = __floats2bfloat162_rn(e2, e3);
                            *(uint32_t*)(smem + AT_P + R[2 * r16 + 1] * ROWB + col * 2) = bf2_to_u32(b);
                            l4[2 * r16 + 1] += __bfloat162float(b.x) + __bfloat162float(b.y);
                        }
            }
            __syncthreads();   // P + V complete

            if (ga) {
                // PV: rows 32g x dv half hf; keys fully inside the loop
#pragma unroll
                for (int s = 0; s < 8; s++) {
                    uint32_t pa0[4], pa1[4];
                    const uint32_t poff = (uint32_t)((s * 16 + kA * 8) * 2);
                    LDSM_X4(pa0[0], pa0[1], pa0[2], pa0[3],
                            sb + AT_P + (uint32_t)(32 * g + rA) * ROWB + poff);
                    LDSM_X4(pa1[0], pa1[1], pa1[2], pa1[3],
                            sb + AT_P + (uint32_t)(32 * g + 16 + rA) * ROWB + poff);
                    const uint32_t vrow = (uint32_t)(s * 16 + rA) * ROWB;
#pragma unroll
                    for (int nv = 0; nv < 8; nv++) {
                        uint32_t bh0, bh1;
                        LDSM_X2_T(bh0, bh1, sb + AT_VH + vrow + (8 * hf + nv) * 16);
                        MMA16816(oa[nv],     pa0, bh0, bh1);
                        MMA16816(oa[8 + nv], pa1, bh0, bh1);
                    }
#pragma unroll
                    for (int nv = 0; nv < 8; nv++) {
                        uint32_t bl0, bl1;
                        LDSM_X2_T(bl0, bl1, sb + AT_VL + vrow + (8 * hf + nv) * 16);
                        MMA16816(oa[nv],     pa0, bl0, bl1);
                        MMA16816(oa[8 + nv], pa1, bl0, bl1);
                    }
                }
            }
        }
    }

    // epilogue: l (quad-reduce, then cross-half via smem), O direct
#pragma unroll
    for (int j = 0; j < 4; j++) {
        l4[j] += __shfl_xor_sync(0xffffffffu, l4[j], 1);
        l4[j] += __shfl_xor_sync(0xffffffffu, l4[j], 2);
    }
    if (c2 == 0) {
#pragma unroll
        for (int j = 0; j < 4; j++) lred[hf * 128 + R[j]] = l4[j];
    }
    __syncthreads();
#pragma unroll
    for (int r16 = 0; r16 < 2; r16++) {
        const int ra = row0 + R[2 * r16], rb = row0 + R[2 * r16 + 1];
#pragma unroll
        for (int nv = 0; nv < 8; nv++) {
            const int f = r16 * 8 + nv;
            const int col = 64 * hf + 8 * nv + 2 * c2;
            float2 v0; v0.x = oa[f][0]; v0.y = oa[f][1];
            float2 v1; v1.x = oa[f][2]; v1.y = oa[f][3];
            *(float2*)&g_O[h][(size_t)ra * DV + col] = v0;
            *(float2*)&g_O[h][(size_t)rb * DV + col] = v1;
        }
    }
    if (hf == 0 && c2 == 0) {
#pragma unroll
        for (int j = 0; j < 4; j++)
            g_l[h][row0 + R[j]] = lred[R[j]] + lred[128 + R[j]];
    }
}

// ============================================================================
// combine: out = (O0 + O1) / (l0 + l1)
// ============================================================================
__global__ __launch_bounds__(256, 4)
void combine_kernel(float* __restrict__ out) {
    const int i4 = blockIdx.x * 256 + threadIdx.x;
    const int rowi = i4 >> 5;
    const float inv = 1.0f / (g_l[0][rowi] + g_l[1][rowi]);
    float4 a = ((const float4*)g_O[0])[i4];
    float4 b = ((const float4*)g_O[1])[i4];
    float4 o = make_float4((a.x + b.x) * inv, (a.y + b.y) * inv,
                           (a.z + b.z) * inv, (a.w + b.w) * inv);
    ((float4*)out)[i4] = o;
}

// ---------------------------------------------------------------------------
extern "C" void kernel_launch(void* const* d_in, const int* in_sizes, int n_in,
                              void* d_out, int out_size) {
    const float* x   = (const float*)d_in[0];
    const float* Wqk = (const float*)d_in[1];
    const float* bqk = (const float*)d_in[2];
    const float* Wv  = (const float*)d_in[3];
    const float* bv  = (const float*)d_in[4];
    float* out = (float*)d_out;

    cudaFuncSetAttribute(proj_hmma_kernel, cudaFuncAttributeMaxDynamicSharedMemorySize, PJ_SMEM);
    cudaFuncSetAttribute(attn_kernel, cudaFuncAttributeMaxDynamicSharedMemorySize, ATT_SMEM);

    proj_hmma_kernel<<<dim3(NTOK / 128, 2), 256, PJ_SMEM>>>(x, Wqk, bqk, Wv, bv);
    attn_kernel<<<dim3(NTOK / 128, 2), 256, ATT_SMEM>>>();
    combine_kernel<<<1024, 256>>>(out);
}

// round 12
// speedup vs baseline: 1.0356x; 1.0356x over previous
#include <cuda_runtime.h>
#include <cuda_bf16.h>
#include <stdint.h>

#define NTOK 8192
#define DIM  1024
#define DK   128
#define DV   128

// ---------------- device globals (allocation-free scratch) ----------------
__device__ float g_v[NTOK * DV];
__device__ __align__(256) __nv_bfloat16 g_qkh[NTOK * DK];   // qk bf16 row-major
__device__ __align__(256) float g_ss[NTOK];                 // ||qk_i||^2 fp32
__device__ __align__(256) float g_O[2][NTOK * DV];          // split-KV numerators
__device__ __align__(256) float g_l[2][NTOK];               // split-KV denominators
__device__ __align__(256) __nv_bfloat16 g_Wh[2][DK * DIM];  // W hi bf16 (0 qk, 1 v)
__device__ __align__(256) __nv_bfloat16 g_Wl[2][DK * DIM];  // W lo bf16

// ---------------- helpers ----------------
__device__ __forceinline__ uint32_t smem_to_u32(const void* p) {
    uint32_t a;
    asm("{ .reg .u64 t; cvta.to.shared.u64 t, %1; cvt.u32.u64 %0, t; }" : "=r"(a) : "l"(p));
    return a;
}
__device__ __forceinline__ void cp16(uint32_t dst, const void* src) {
    asm volatile("cp.async.cg.shared.global [%0], [%1], 16;" :: "r"(dst), "l"(src) : "memory");
}
#define CP_COMMIT() asm volatile("cp.async.commit_group;" ::: "memory")
#define CP_WAIT0()  asm volatile("cp.async.wait_group 0;" ::: "memory")
#define CP_WAIT1()  asm volatile("cp.async.wait_group 1;" ::: "memory")

__device__ __forceinline__ uint32_t bf2_to_u32(__nv_bfloat162 v) {
    uint32_t u; *(__nv_bfloat162*)&u = v; return u;
}

#define LDSM_X4(r0, r1, r2, r3, a) \
    asm volatile("ldmatrix.sync.aligned.m8n8.x4.shared.b16 {%0,%1,%2,%3}, [%4];" \
                 : "=r"(r0), "=r"(r1), "=r"(r2), "=r"(r3) : "r"(a))
#define LDSM_X2_T(r0, r1, a) \
    asm volatile("ldmatrix.sync.aligned.m8n8.x2.trans.shared.b16 {%0,%1}, [%2];" \
                 : "=r"(r0), "=r"(r1) : "r"(a))
// D(f32 4) += A(bf16 16x16) * B(bf16 16x8 col)
#define MMA16816(d, a, b0, b1) \
    asm volatile("mma.sync.aligned.m16n8k16.row.col.f32.bf16.bf16.f32 " \
                 "{%0,%1,%2,%3}, {%4,%5,%6,%7}, {%8,%9}, {%0,%1,%2,%3};" \
                 : "+f"((d)[0]), "+f"((d)[1]), "+f"((d)[2]), "+f"((d)[3]) \
                 : "r"((a)[0]), "r"((a)[1]), "r"((a)[2]), "r"((a)[3]), "r"(b0), "r"(b1))

// ============================================================================
// prep_w: Wqk/Wv fp32 -> global bf16 hi/lo (once; removes 64x redundant convert)
// grid (32, 2) x 256 thr; each thread 16 floats.
// ============================================================================
__global__ __launch_bounds__(256, 4)
void prep_w_kernel(const float* __restrict__ Wqk, const float* __restrict__ Wv) {
    const int type = blockIdx.y;
    const float* W = type ? Wv : Wqk;
    __nv_bfloat16* dh = g_Wh[type];
    __nv_bfloat16* dl = g_Wl[type];
    const int base = (blockIdx.x * 256 + threadIdx.x) * 16;
#pragma unroll
    for (int j = 0; j < 4; j++) {
        float4 f = *(const float4*)&W[base + j * 4];
        __nv_bfloat162 h0 = __floats2bfloat162_rn(f.x, f.y);
        __nv_bfloat162 h1 = __floats2bfloat162_rn(f.z, f.w);
        __nv_bfloat162 l0 = __floats2bfloat162_rn(f.x - __bfloat162float(h0.x),
                                                  f.y - __bfloat162float(h0.y));
        __nv_bfloat162 l1 = __floats2bfloat162_rn(f.z - __bfloat162float(h1.x),
                                                  f.w - __bfloat162float(h1.y));
        uint2 uh; uh.x = bf2_to_u32(h0); uh.y = bf2_to_u32(h1);
        uint2 ul; ul.x = bf2_to_u32(l0); ul.y = bf2_to_u32(l1);
        *(uint2*)&dh[base + j * 4] = uh;
        *(uint2*)&dl[base + j * 4] = ul;
    }
}

// ============================================================================
// proj v2 (HMMA, bf16 hi/lo 3-product): double-buffered A/B/staging pipeline,
// ONE sync per chunk. B tiles loaded pre-converted from g_Wh/g_Wl.
// smem: A[2] (AH+AL) 73728 | B[2] (BH+BL) 73728 | xstage[2] 65536 = 212992
// ============================================================================
#define PJ_ROWB 144
#define PJ_A(b) ((b) * 36864)
#define PJ_B(b) (73728 + (b) * 36864)
#define PJ_S(b) (147456 + (b) * 32768)
#define PJ_SMEM 212992

__global__ __launch_bounds__(256, 1)
void proj_hmma_kernel(const float* __restrict__ x,
                      const float* __restrict__ bqk, const float* __restrict__ bv) {
    extern __shared__ char smem[];
    const uint32_t sb = smem_to_u32(smem);
    const int tid = threadIdx.x, wid = tid >> 5, lane = tid & 31;
    const int row0 = blockIdx.x * 128;
    const int type = blockIdx.y;
    const float* bias = type ? bv : bqk;
    const __nv_bfloat16* Wh = g_Wh[type];
    const __nv_bfloat16* Wl = g_Wl[type];

    const int rA = ((lane >> 3) & 1) * 8 + (lane & 7);
    const int kA = (lane >> 4) & 1;
    const int rB = ((lane >> 4) & 1) * 8 + (lane & 7);
    const int kB = (lane >> 3) & 1;

    float acc[16][4];
#pragma unroll
    for (int nt = 0; nt < 16; nt++)
#pragma unroll
        for (int q = 0; q < 4; q++) acc[nt][q] = 0.f;

    // ---- load helpers (8 cp16/thread each) ----
    // x chunk kk -> staging buf s
    auto load_x = [&](int kk, int s) {
#pragma unroll
        for (int it = 0; it < 8; it++) {
            int idx = it * 256 + tid;
            int r = idx >> 4, q = idx & 15;
            cp16(sb + PJ_S(s) + r * 256 + q * 16, &x[(size_t)(row0 + r) * DIM + kk + q * 4]);
        }
    };
    // W chunk kk (hi+lo) -> B tile buf b
    auto load_B = [&](int kk, int b) {
#pragma unroll
        for (int it = 0; it < 8; it++) {
            int idx = it * 256 + tid;
            int r = idx >> 4, sel = (idx >> 3) & 1, cc = idx & 7;
            const __nv_bfloat16* src = sel ? Wl : Wh;
            cp16(sb + PJ_B(b) + sel * 18432 + r * PJ_ROWB + cc * 16,
                 &src[(size_t)r * DIM + kk + cc * 8]);
        }
    };
    // convert staging buf s -> A tile buf b
    auto convert_A = [&](int s, int b) {
#pragma unroll
        for (int it = 0; it < 8; it++) {
            int idx = it * 256 + tid;
            int r = idx >> 4, kq = (idx & 15) * 4;
            float4 fa = *(const float4*)(smem + PJ_S(s) + r * 256 + kq * 4);
            __nv_bfloat162 h0 = __floats2bfloat162_rn(fa.x, fa.y);
            __nv_bfloat162 h1 = __floats2bfloat162_rn(fa.z, fa.w);
            __nv_bfloat162 l0 = __floats2bfloat162_rn(fa.x - __bfloat162float(h0.x),
                                                      fa.y - __bfloat162float(h0.y));
            __nv_bfloat162 l1 = __floats2bfloat162_rn(fa.z - __bfloat162float(h1.x),
                                                      fa.w - __bfloat162float(h1.y));
            uint2 u;
            u.x = bf2_to_u32(h0); u.y = bf2_to_u32(h1);
            *(uint2*)(smem + PJ_A(b) + r * PJ_ROWB + kq * 2) = u;
            u.x = bf2_to_u32(l0); u.y = bf2_to_u32(l1);
            *(uint2*)(smem + PJ_A(b) + 18432 + r * PJ_ROWB + kq * 2) = u;
        }
    };

    // ---- prologue ----
    load_x(0, 0); load_B(0, 0); CP_COMMIT();    // group: x(0), B(0)
    load_x(64, 1); CP_COMMIT();                 // group: x(1)
    CP_WAIT1(); __syncthreads();                // x(0)/B(0) ready
    convert_A(0, 0);

    for (int c = 0; c < 16; c++) {
        const int cb = c & 1, nb = cb ^ 1;
        CP_WAIT0();
        __syncthreads();   // everything issued last iter arrived; prev MMA/convert done

        // issue next loads (overlap with convert+MMA below)
        if (c + 2 < 16) load_x((c + 2) * 64, cb);
        if (c + 1 < 16) load_B((c + 1) * 64, nb);
        CP_COMMIT();

        // convert chunk c+1 into A[nb]
        if (c + 1 < 16) convert_A(nb, nb);

        // MMA chunk c from A[cb], B[cb]
        uint32_t ah[4][4], al[4][4];
        const uint32_t arh = sb + PJ_A(cb) + (uint32_t)(wid * 16 + rA) * PJ_ROWB;
#pragma unroll
        for (int s = 0; s < 4; s++) {
            LDSM_X4(ah[s][0], ah[s][1], ah[s][2], ah[s][3], arh + (s * 16 + kA * 8) * 2);
            LDSM_X4(al[s][0], al[s][1], al[s][2], al[s][3], arh + 18432 + (s * 16 + kA * 8) * 2);
        }
#pragma unroll
        for (int s = 0; s < 4; s++) {
#pragma unroll
            for (int ng = 0; ng < 8; ng++) {
                uint32_t bh0, bh1, bh2, bh3, bl0, bl1, bl2, bl3;
                const uint32_t boff = sb + PJ_B(cb) + (uint32_t)(ng * 16 + rB) * PJ_ROWB
                                      + (s * 16 + kB * 8) * 2;
                LDSM_X4(bh0, bh1, bh2, bh3, boff);
                LDSM_X4(bl0, bl1, bl2, bl3, boff + 18432);
                MMA16816(acc[2 * ng],     ah[s], bh0, bh1);
                MMA16816(acc[2 * ng + 1], ah[s], bh2, bh3);
                MMA16816(acc[2 * ng],     ah[s], bl0, bl1);
                MMA16816(acc[2 * ng + 1], ah[s], bl2, bl3);
                MMA16816(acc[2 * ng],     al[s], bh0, bh1);
                MMA16816(acc[2 * ng + 1], al[s], bh2, bh3);
            }
        }
    }

    // ---- epilogue (unchanged) ----
    const int rl = row0 + wid * 16 + (lane >> 2);
    const int rh = rl + 8;
    if (type == 0) {
        float ss0 = 0.f, ss1 = 0.f;
#pragma unroll
        for (int nt = 0; nt < 16; nt++) {
            const int col = nt * 8 + 2 * (lane & 3);
            float2 bb = *(const float2*)&bias[col];
            float c0 = acc[nt][0] + bb.x, c1 = acc[nt][1] + bb.y;
            float c2 = acc[nt][2] + bb.x, c3 = acc[nt][3] + bb.y;
            ss0 += c0 * c0 + c1 * c1;
            ss1 += c2 * c2 + c3 * c3;
            *(uint32_t*)&g_qkh[(size_t)rl * DK + col] = bf2_to_u32(__floats2bfloat162_rn(c0, c1));
            *(uint32_t*)&g_qkh[(size_t)rh * DK + col] = bf2_to_u32(__floats2bfloat162_rn(c2, c3));
        }
        ss0 += __shfl_xor_sync(0xffffffffu, ss0, 1);
        ss0 += __shfl_xor_sync(0xffffffffu, ss0, 2);
        ss1 += __shfl_xor_sync(0xffffffffu, ss1, 1);
        ss1 += __shfl_xor_sync(0xffffffffu, ss1, 2);
        if ((lane & 3) == 0) { g_ss[rl] = ss0; g_ss[rh] = ss1; }
    } else {
#pragma unroll
        for (int nt = 0; nt < 16; nt++) {
            const int col = nt * 8 + 2 * (lane & 3);
            float2 bb = *(const float2*)&bias[col];
            float2 v0; v0.x = acc[nt][0] + bb.x; v0.y = acc[nt][1] + bb.y;
            float2 v1; v1.x = acc[nt][2] + bb.x; v1.y = acc[nt][3] + bb.y;
            *(float2*)&g_v[(size_t)rl * DV + col] = v0;
            *(float2*)&g_v[(size_t)rh * DV + col] = v1;
        }
    }
}

// ============================================================================
// attention (HMMA): BM=128, 256 thr, split-KV x2, margin 14 — R10 proven, verbatim
// ============================================================================
#define ROWB 272
#define AT_K0 0
#define AT_K1 34816
#define AT_VH 69632
#define AT_VL 104448
#define AT_FLAGS 139264
#define ATT_SMEM (AT_FLAGS + 64)

__global__ __launch_bounds__(256, 1)
void attn_kernel() {
    extern __shared__ char smem[];
    const uint32_t sb = smem_to_u32(smem);
    int* flags = (int*)(smem + AT_FLAGS);
    const int tid = threadIdx.x, wid = tid >> 5, lane = tid & 31;
    const int row0 = blockIdx.x * 128;
    const int h = blockIdx.y;
    const int j0base = h * 4096;

    const int rA = ((lane >> 3) & 1) * 8 + (lane & 7);
    const int kA = (lane >> 4) & 1;
    const int rB = ((lane >> 4) & 1) * 8 + (lane & 7);
    const int kB = (lane >> 3) & 1;

    const int rl = row0 + wid * 16 + (lane >> 2);
    const int rh = rl + 8;
    const float m0 = g_ss[rl], m1 = g_ss[rh];
    const float thr0 = m0 - 14.f, thr1 = m1 - 14.f;

#pragma unroll
    for (int it = 0; it < 8; it++) {
        int c = it * 256 + tid;
        int r = c >> 4, cc = (c & 15) * 8;
        cp16(sb + AT_VH + r * ROWB + cc * 2, &g_qkh[(size_t)(row0 + r) * DK + cc]);
        cp16(sb + AT_K0 + r * ROWB + cc * 2, &g_qkh[(size_t)(j0base + r) * DK + cc]);
    }
    CP_COMMIT(); CP_WAIT0();
    __syncthreads();

    uint32_t qa[8][4];
    {
        const uint32_t qrow = sb + AT_VH + (uint32_t)(wid * 16 + rA) * ROWB;
#pragma unroll
        for (int s = 0; s < 8; s++)
            LDSM_X4(qa[s][0], qa[s][1], qa[s][2], qa[s][3], qrow + (s * 16 + kA * 8) * 2);
    }
    __syncthreads();   // Q reads done before VH reused for V

    float oa[16][4];
#pragma unroll
    for (int nt = 0; nt < 16; nt++)
#pragma unroll
        for (int q = 0; q < 4; q++) oa[nt][q] = 0.f;
    float l0 = 0.f, l1 = 0.f;

    for (int t = 0; t < 32; t++) {
        if (t > 0) CP_WAIT0();
        __syncthreads();

        if (t + 1 < 32) {
            const uint32_t nb = sb + ((t & 1) ? AT_K0 : AT_K1);
            const int j1 = j0base + (t + 1) * 128;
#pragma unroll
            for (int it = 0; it < 8; it++) {
                int c = it * 256 + tid;
                int r = c >> 4, cc = (c & 15) * 8;
                cp16(nb + r * ROWB + cc * 2, &g_qkh[(size_t)(j1 + r) * DK + cc]);
            }
            CP_COMMIT();
        }

        const uint32_t kb = sb + ((t & 1) ? AT_K1 : AT_K0);
        float sa[16][4];
#pragma unroll
        for (int nt = 0; nt < 16; nt++)
#pragma unroll
            for (int q = 0; q < 4; q++) sa[nt][q] = 0.f;
#pragma unroll
        for (int s = 0; s < 8; s++) {
            const uint32_t kcol = kb + (uint32_t)((s * 16 + kB * 8) * 2);
#pragma unroll
            for (int np = 0; np < 8; np++) {
                uint32_t b0, b1, b2, b3;
                LDSM_X4(b0, b1, b2, b3, kcol + (uint32_t)(np * 16 + rB) * ROWB);
                MMA16816(sa[2 * np],     qa[s], b0, b1);
                MMA16816(sa[2 * np + 1], qa[s], b2, b3);
            }
        }

        float mx0 = -3.0e38f, mx1 = -3.0e38f;
#pragma unroll
        for (int nt = 0; nt < 16; nt++) {
            mx0 = fmaxf(mx0, fmaxf(sa[nt][0], sa[nt][1]));
            mx1 = fmaxf(mx1, fmaxf(sa[nt][2], sa[nt][3]));
        }
        mx0 = fmaxf(mx0, __shfl_xor_sync(0xffffffffu, mx0, 1));
        mx0 = fmaxf(mx0, __shfl_xor_sync(0xffffffffu, mx0, 2));
        mx1 = fmaxf(mx1, __shfl_xor_sync(0xffffffffu, mx1, 1));
        mx1 = fmaxf(mx1, __shfl_xor_sync(0xffffffffu, mx1, 2));
        const bool act0 = mx0 >= thr0, act1 = mx1 >= thr1;
        const int wact = __any_sync(0xffffffffu, act0 || act1);
        if (lane == 0) flags[wid] = wact;
        __syncthreads();
        int cact = 0;
#pragma unroll
        for (int w = 0; w < 8; w++) cact |= flags[w];

        if (cact) {
            const int j0 = j0base + t * 128;
#pragma unroll
            for (int it = 0; it < 16; it++) {
                int idx = it * 256 + tid;
                int r = idx >> 5, cq = (idx & 31) * 4;
                float4 f = *(const float4*)&g_v[(size_t)(j0 + r) * DV + cq];
                __nv_bfloat162 h0 = __floats2bfloat162_rn(f.x, f.y);
                __nv_bfloat162 h1 = __floats2bfloat162_rn(f.z, f.w);
                __nv_bfloat162 e0 = __floats2bfloat162_rn(f.x - __bfloat162float(h0.x),
                                                          f.y - __bfloat162float(h0.y));
                __nv_bfloat162 e1 = __floats2bfloat162_rn(f.z - __bfloat162float(h1.x),
                                                          f.w - __bfloat162float(h1.y));
                uint2 uh; uh.x = bf2_to_u32(h0); uh.y = bf2_to_u32(h1);
                uint2 ul; ul.x = bf2_to_u32(e0); ul.y = bf2_to_u32(e1);
                *(uint2*)(smem + AT_VH + r * ROWB + cq * 2) = uh;
                *(uint2*)(smem + AT_VL + r * ROWB + cq * 2) = ul;
            }
            __syncthreads();

            if (wact) {
#pragma unroll
                for (int s = 0; s < 8; s++) {
                    uint32_t pa[4];
                    float e00 = act0 ? __expf(sa[2 * s][0] - m0) : 0.f;
                    float e01 = act0 ? __expf(sa[2 * s][1] - m0) : 0.f;
                    float e10 = act1 ? __expf(sa[2 * s][2] - m1) : 0.f;
                    float e11 = act1 ? __expf(sa[2 * s][3] - m1) : 0.f;
                    float f00 = act0 ? __expf(sa[2 * s + 1][0] - m0) : 0.f;
                    float f01 = act0 ? __expf(sa[2 * s + 1][1] - m0) : 0.f;
                    float f10 = act1 ? __expf(sa[2 * s + 1][2] - m1) : 0.f;
                    float f11 = act1 ? __expf(sa[2 * s + 1][3] - m1) : 0.f;
                    __nv_bfloat162 b;
                    b = __floats2bfloat162_rn(e00, e01); pa[0] = bf2_to_u32(b);
                    l0 += __bfloat162float(b.x) + __bfloat162float(b.y);
                    b = __floats2bfloat162_rn(e10, e11); pa[1] = bf2_to_u32(b);
                    l1 += __bfloat162float(b.x) + __bfloat162float(b.y);
                    b = __floats2bfloat162_rn(f00, f01); pa[2] = bf2_to_u32(b);
                    l0 += __bfloat162float(b.x) + __bfloat162float(b.y);
                    b = __floats2bfloat162_rn(f10, f11); pa[3] = bf2_to_u32(b);
                    l1 += __bfloat162float(b.x) + __bfloat162float(b.y);

                    const uint32_t vrow = (uint32_t)(s * 16 + rA) * ROWB;
#pragma unroll
                    for (int nt = 0; nt < 16; nt++) {
                        uint32_t bh0, bh1;
                        LDSM_X2_T(bh0, bh1, sb + AT_VH + vrow + nt * 16);
                        MMA16816(oa[nt], pa, bh0, bh1);
                    }
#pragma unroll
                    for (int nt = 0; nt < 16; nt++) {
                        uint32_t bl0, bl1;
                        LDSM_X2_T(bl0, bl1, sb + AT_VL + vrow + nt * 16);
                        MMA16816(oa[nt], pa, bl0, bl1);
                    }
                }
            }
        }
    }

    l0 += __shfl_xor_sync(0xffffffffu, l0, 1);
    l0 += __shfl_xor_sync(0xffffffffu, l0, 2);
    l1 += __shfl_xor_sync(0xffffffffu, l1, 1);
    l1 += __shfl_xor_sync(0xffffffffu, l1, 2);
#pragma unroll
    for (int nt = 0; nt < 16; nt++) {
        const int col = nt * 8 + 2 * (lane & 3);
        float2 v0; v0.x = oa[nt][0]; v0.y = oa[nt][1];
        float2 v1; v1.x = oa[nt][2]; v1.y = oa[nt][3];
        *(float2*)&g_O[h][(size_t)rl * DV + col] = v0;
        *(float2*)&g_O[h][(size_t)rh * DV + col] = v1;
    }
    if ((lane & 3) == 0) {
        g_l[h][rl] = l0;
        g_l[h][rh] = l1;
    }
}

// ============================================================================
// combine: out = (O0 + O1) / (l0 + l1)
// ============================================================================
__global__ __launch_bounds__(256, 4)
void combine_kernel(float* __restrict__ out) {
    const int i4 = blockIdx.x * 256 + threadIdx.x;
    const int rowi = i4 >> 5;
    const float inv = 1.0f / (g_l[0][rowi] + g_l[1][rowi]);
    float4 a = ((const float4*)g_O[0])[i4];
    float4 b = ((const float4*)g_O[1])[i4];
    float4 o = make_float4((a.x + b.x) * inv, (a.y + b.y) * inv,
                           (a.z + b.z) * inv, (a.w + b.w) * inv);
    ((float4*)out)[i4] = o;
}

// ---------------------------------------------------------------------------
extern "C" void kernel_launch(void* const* d_in, const int* in_sizes, int n_in,
                              void* d_out, int out_size) {
    const float* x   = (const float*)d_in[0];
    const float* Wqk = (const float*)d_in[1];
    const float* bqk = (const float*)d_in[2];
    const float* Wv  = (const float*)d_in[3];
    const float* bv  = (const float*)d_in[4];
    float* out = (float*)d_out;

    cudaFuncSetAttribute(proj_hmma_kernel, cudaFuncAttributeMaxDynamicSharedMemorySize, PJ_SMEM);
    cudaFuncSetAttribute(attn_kernel, cudaFuncAttributeMaxDynamicSharedMemorySize, ATT_SMEM);

    prep_w_kernel<<<dim3(32, 2), 256>>>(Wqk, Wv);
    proj_hmma_kernel<<<dim3(NTOK / 128, 2), 256, PJ_SMEM>>>(x, bqk, bv);
    attn_kernel<<<dim3(NTOK / 128, 2), 256, ATT_SMEM>>>();
    combine_kernel<<<1024, 256>>>(out);
}

// round 13
// speedup vs baseline: 1.0523x; 1.0161x over previous
#include <cuda_runtime.h>
#include <cuda_bf16.h>
#include <stdint.h>

#define NTOK 8192
#define DIM  1024
#define DK   128
#define DV   128

// ---------------- device globals (allocation-free scratch) ----------------
__device__ float g_v[NTOK * DV];
__device__ __align__(256) __nv_bfloat16 g_qkh[NTOK * DK];   // qk bf16 row-major
__device__ __align__(256) float g_ss[NTOK];                 // ||qk_i||^2 fp32
__device__ __align__(256) float g_O[2][NTOK * DV];          // split-KV numerators
__device__ __align__(256) float g_l[2][NTOK];               // split-KV denominators

// ---------------- helpers ----------------
__device__ __forceinline__ uint32_t smem_to_u32(const void* p) {
    uint32_t a;
    asm("{ .reg .u64 t; cvta.to.shared.u64 t, %1; cvt.u32.u64 %0, t; }" : "=r"(a) : "l"(p));
    return a;
}
__device__ __forceinline__ void cp16(uint32_t dst, const void* src) {
    asm volatile("cp.async.cg.shared.global [%0], [%1], 16;" :: "r"(dst), "l"(src) : "memory");
}
#define CP_COMMIT() asm volatile("cp.async.commit_group;" ::: "memory")
#define CP_WAIT0()  asm volatile("cp.async.wait_group 0;" ::: "memory")

__device__ __forceinline__ uint32_t bf2_to_u32(__nv_bfloat162 v) {
    uint32_t u; *(__nv_bfloat162*)&u = v; return u;
}

#define LDSM_X4(r0, r1, r2, r3, a) \
    asm volatile("ldmatrix.sync.aligned.m8n8.x4.shared.b16 {%0,%1,%2,%3}, [%4];" \
                 : "=r"(r0), "=r"(r1), "=r"(r2), "=r"(r3) : "r"(a))
#define LDSM_X2_T(r0, r1, a) \
    asm volatile("ldmatrix.sync.aligned.m8n8.x2.trans.shared.b16 {%0,%1}, [%2];" \
                 : "=r"(r0), "=r"(r1) : "r"(a))
// D(f32 4) += A(bf16 16x16) * B(bf16 16x8 col)
#define MMA16816(d, a, b0, b1) \
    asm volatile("mma.sync.aligned.m16n8k16.row.col.f32.bf16.bf16.f32 " \
                 "{%0,%1,%2,%3}, {%4,%5,%6,%7}, {%8,%9}, {%0,%1,%2,%3};" \
                 : "+f"((d)[0]), "+f"((d)[1]), "+f"((d)[2]), "+f"((d)[3]) \
                 : "r"((a)[0]), "r"((a)[1]), "r"((a)[2]), "r"((a)[3]), "r"(b0), "r"(b1))

// ============================================================================
// proj (HMMA, bf16 hi/lo split): R10 code with ONE change — type 0 (qk) drops
// the al*bh product (x_lo error is below the bf16 rounding applied to qk).
// type 1 (v) keeps all 3 products (feeds output directly).
// ============================================================================
#define PJ_ROWB 144
#define PJ_AH 0
#define PJ_AL 18432
#define PJ_BH 36864
#define PJ_BL 55296
#define PJ_SA 73728
#define PJ_SB 106496
#define PJ_SMEM 139264

__global__ __launch_bounds__(256, 1)
void proj_hmma_kernel(const float* __restrict__ x,
                      const float* __restrict__ Wqk, const float* __restrict__ bqk,
                      const float* __restrict__ Wv,  const float* __restrict__ bv) {
    extern __shared__ char smem[];
    const uint32_t sb = smem_to_u32(smem);
    const int tid = threadIdx.x, wid = tid >> 5, lane = tid & 31;
    const int row0 = blockIdx.x * 128;
    const int type = blockIdx.y;
    const float* W = type ? Wv : Wqk;
    const float* bias = type ? bv : bqk;

    const int rA = ((lane >> 3) & 1) * 8 + (lane & 7);
    const int kA = (lane >> 4) & 1;
    const int rB = ((lane >> 4) & 1) * 8 + (lane & 7);
    const int kB = (lane >> 3) & 1;

    float acc[16][4];
#pragma unroll
    for (int nt = 0; nt < 16; nt++)
#pragma unroll
        for (int q = 0; q < 4; q++) acc[nt][q] = 0.f;

#pragma unroll
    for (int it = 0; it < 8; it++) {
        int idx = it * 256 + tid;
        int r = idx >> 4, kq = (idx & 15) * 4;
        cp16(sb + PJ_SA + r * 256 + kq * 4, &x[(size_t)(row0 + r) * DIM + kq]);
        cp16(sb + PJ_SB + r * 256 + kq * 4, &W[(size_t)r * DIM + kq]);
    }
    CP_COMMIT();

    for (int c = 0; c < 16; c++) {
        CP_WAIT0();
        __syncthreads();

#pragma unroll
        for (int it = 0; it < 8; it++) {
            int idx = it * 256 + tid;
            int r = idx >> 4, kq = (idx & 15) * 4;
            float4 fa = *(const float4*)(smem + PJ_SA + r * 256 + kq * 4);
            float4 fb = *(const float4*)(smem + PJ_SB + r * 256 + kq * 4);
            __nv_bfloat162 ah0 = __floats2bfloat162_rn(fa.x, fa.y);
            __nv_bfloat162 ah1 = __floats2bfloat162_rn(fa.z, fa.w);
            __nv_bfloat162 bh0 = __floats2bfloat162_rn(fb.x, fb.y);
            __nv_bfloat162 bh1 = __floats2bfloat162_rn(fb.z, fb.w);
            __nv_bfloat162 bl0 = __floats2bfloat162_rn(fb.x - __bfloat162float(bh0.x),
                                                       fb.y - __bfloat162float(bh0.y));
            __nv_bfloat162 bl1 = __floats2bfloat162_rn(fb.z - __bfloat162float(bh1.x),
                                                       fb.w - __bfloat162float(bh1.y));
            uint2 u;
            u.x = bf2_to_u32(ah0); u.y = bf2_to_u32(ah1);
            *(uint2*)(smem + PJ_AH + r * PJ_ROWB + kq * 2) = u;
            if (type) {   // AL only needed for v's third product
                __nv_bfloat162 al0 = __floats2bfloat162_rn(fa.x - __bfloat162float(ah0.x),
                                                           fa.y - __bfloat162float(ah0.y));
                __nv_bfloat162 al1 = __floats2bfloat162_rn(fa.z - __bfloat162float(ah1.x),
                                                           fa.w - __bfloat162float(ah1.y));
                u.x = bf2_to_u32(al0); u.y = bf2_to_u32(al1);
                *(uint2*)(smem + PJ_AL + r * PJ_ROWB + kq * 2) = u;
            }
            u.x = bf2_to_u32(bh0); u.y = bf2_to_u32(bh1);
            *(uint2*)(smem + PJ_BH + r * PJ_ROWB + kq * 2) = u;
            u.x = bf2_to_u32(bl0); u.y = bf2_to_u32(bl1);
            *(uint2*)(smem + PJ_BL + r * PJ_ROWB + kq * 2) = u;
        }
        __syncthreads();

        if (c + 1 < 16) {
            const int kk = (c + 1) * 64;
#pragma unroll
            for (int it = 0; it < 8; it++) {
                int idx = it * 256 + tid;
                int r = idx >> 4, kq = (idx & 15) * 4;
                cp16(sb + PJ_SA + r * 256 + kq * 4, &x[(size_t)(row0 + r) * DIM + kk + kq]);
                cp16(sb + PJ_SB + r * 256 + kq * 4, &W[(size_t)r * DIM + kk + kq]);
            }
            CP_COMMIT();
        }

        uint32_t ah[4][4], al[4][4];
        const uint32_t arh = sb + PJ_AH + (uint32_t)(wid * 16 + rA) * PJ_ROWB;
        const uint32_t arl = sb + PJ_AL + (uint32_t)(wid * 16 + rA) * PJ_ROWB;
#pragma unroll
        for (int s = 0; s < 4; s++) {
            LDSM_X4(ah[s][0], ah[s][1], ah[s][2], ah[s][3], arh + (s * 16 + kA * 8) * 2);
            if (type)
                LDSM_X4(al[s][0], al[s][1], al[s][2], al[s][3], arl + (s * 16 + kA * 8) * 2);
        }

#pragma unroll
        for (int s = 0; s < 4; s++) {
#pragma unroll
            for (int ng = 0; ng < 8; ng++) {
                uint32_t bh0, bh1, bh2, bh3, bl0, bl1, bl2, bl3;
                const uint32_t boff = (uint32_t)(ng * 16 + rB) * PJ_ROWB + (s * 16 + kB * 8) * 2;
                LDSM_X4(bh0, bh1, bh2, bh3, sb + PJ_BH + boff);
                LDSM_X4(bl0, bl1, bl2, bl3, sb + PJ_BL + boff);
                MMA16816(acc[2 * ng],     ah[s], bh0, bh1);
                MMA16816(acc[2 * ng + 1], ah[s], bh2, bh3);
                MMA16816(acc[2 * ng],     ah[s], bl0, bl1);
                MMA16816(acc[2 * ng + 1], ah[s], bl2, bl3);
                if (type) {
                    MMA16816(acc[2 * ng],     al[s], bh0, bh1);
                    MMA16816(acc[2 * ng + 1], al[s], bh2, bh3);
                }
            }
        }
    }

    const int rl = row0 + wid * 16 + (lane >> 2);
    const int rh = rl + 8;
    if (type == 0) {
        float ss0 = 0.f, ss1 = 0.f;
#pragma unroll
        for (int nt = 0; nt < 16; nt++) {
            const int col = nt * 8 + 2 * (lane & 3);
            float2 bb = *(const float2*)&bias[col];
            float c0 = acc[nt][0] + bb.x, c1 = acc[nt][1] + bb.y;
            float c2 = acc[nt][2] + bb.x, c3 = acc[nt][3] + bb.y;
            ss0 += c0 * c0 + c1 * c1;
            ss1 += c2 * c2 + c3 * c3;
            *(uint32_t*)&g_qkh[(size_t)rl * DK + col] = bf2_to_u32(__floats2bfloat162_rn(c0, c1));
            *(uint32_t*)&g_qkh[(size_t)rh * DK + col] = bf2_to_u32(__floats2bfloat162_rn(c2, c3));
        }
        ss0 += __shfl_xor_sync(0xffffffffu, ss0, 1);
        ss0 += __shfl_xor_sync(0xffffffffu, ss0, 2);
        ss1 += __shfl_xor_sync(0xffffffffu, ss1, 1);
        ss1 += __shfl_xor_sync(0xffffffffu, ss1, 2);
        if ((lane & 3) == 0) { g_ss[rl] = ss0; g_ss[rh] = ss1; }
    } else {
#pragma unroll
        for (int nt = 0; nt < 16; nt++) {
            const int col = nt * 8 + 2 * (lane & 3);
            float2 bb = *(const float2*)&bias[col];
            float2 v0; v0.x = acc[nt][0] + bb.x; v0.y = acc[nt][1] + bb.y;
            float2 v1; v1.x = acc[nt][2] + bb.x; v1.y = acc[nt][3] + bb.y;
            *(float2*)&g_v[(size_t)rl * DV + col] = v0;
            *(float2*)&g_v[(size_t)rh * DV + col] = v1;
        }
    }
}

// ============================================================================
// attention (HMMA): BM=128, 256 thr, split-KV x2, margin 14 — R10 champion, verbatim
// ============================================================================
#define ROWB 272
#define AT_K0 0
#define AT_K1 34816
#define AT_VH 69632
#define AT_VL 104448
#define AT_FLAGS 139264
#define ATT_SMEM (AT_FLAGS + 64)

__global__ __launch_bounds__(256, 1)
void attn_kernel() {
    extern __shared__ char smem[];
    const uint32_t sb = smem_to_u32(smem);
    int* flags = (int*)(smem + AT_FLAGS);
    const int tid = threadIdx.x, wid = tid >> 5, lane = tid & 31;
    const int row0 = blockIdx.x * 128;
    const int h = blockIdx.y;
    const int j0base = h * 4096;

    const int rA = ((lane >> 3) & 1) * 8 + (lane & 7);
    const int kA = (lane >> 4) & 1;
    const int rB = ((lane >> 4) & 1) * 8 + (lane & 7);
    const int kB = (lane >> 3) & 1;

    const int rl = row0 + wid * 16 + (lane >> 2);
    const int rh = rl + 8;
    const float m0 = g_ss[rl], m1 = g_ss[rh];
    const float thr0 = m0 - 14.f, thr1 = m1 - 14.f;

#pragma unroll
    for (int it = 0; it < 8; it++) {
        int c = it * 256 + tid;
        int r = c >> 4, cc = (c & 15) * 8;
        cp16(sb + AT_VH + r * ROWB + cc * 2, &g_qkh[(size_t)(row0 + r) * DK + cc]);
        cp16(sb + AT_K0 + r * ROWB + cc * 2, &g_qkh[(size_t)(j0base + r) * DK + cc]);
    }
    CP_COMMIT(); CP_WAIT0();
    __syncthreads();

    uint32_t qa[8][4];
    {
        const uint32_t qrow = sb + AT_VH + (uint32_t)(wid * 16 + rA) * ROWB;
#pragma unroll
        for (int s = 0; s < 8; s++)
            LDSM_X4(qa[s][0], qa[s][1], qa[s][2], qa[s][3], qrow + (s * 16 + kA * 8) * 2);
    }
    __syncthreads();   // Q reads done before VH reused for V

    float oa[16][4];
#pragma unroll
    for (int nt = 0; nt < 16; nt++)
#pragma unroll
        for (int q = 0; q < 4; q++) oa[nt][q] = 0.f;
    float l0 = 0.f, l1 = 0.f;

    for (int t = 0; t < 32; t++) {
        if (t > 0) CP_WAIT0();
        __syncthreads();

        if (t + 1 < 32) {
            const uint32_t nb = sb + ((t & 1) ? AT_K0 : AT_K1);
            const int j1 = j0base + (t + 1) * 128;
#pragma unroll
            for (int it = 0; it < 8; it++) {
                int c = it * 256 + tid;
                int r = c >> 4, cc = (c & 15) * 8;
                cp16(nb + r * ROWB + cc * 2, &g_qkh[(size_t)(j1 + r) * DK + cc]);
            }
            CP_COMMIT();
        }

        const uint32_t kb = sb + ((t & 1) ? AT_K1 : AT_K0);
        float sa[16][4];
#pragma unroll
        for (int nt = 0; nt < 16; nt++)
#pragma unroll
            for (int q = 0; q < 4; q++) sa[nt][q] = 0.f;
#pragma unroll
        for (int s = 0; s < 8; s++) {
            const uint32_t kcol = kb + (uint32_t)((s * 16 + kB * 8) * 2);
#pragma unroll
            for (int np = 0; np < 8; np++) {
                uint32_t b0, b1, b2, b3;
                LDSM_X4(b0, b1, b2, b3, kcol + (uint32_t)(np * 16 + rB) * ROWB);
                MMA16816(sa[2 * np],     qa[s], b0, b1);
                MMA16816(sa[2 * np + 1], qa[s], b2, b3);
            }
        }

        float mx0 = -3.0e38f, mx1 = -3.0e38f;
#pragma unroll
        for (int nt = 0; nt < 16; nt++) {
            mx0 = fmaxf(mx0, fmaxf(sa[nt][0], sa[nt][1]));
            mx1 = fmaxf(mx1, fmaxf(sa[nt][2], sa[nt][3]));
        }
        mx0 = fmaxf(mx0, __shfl_xor_sync(0xffffffffu, mx0, 1));
        mx0 = fmaxf(mx0, __shfl_xor_sync(0xffffffffu, mx0, 2));
        mx1 = fmaxf(mx1, __shfl_xor_sync(0xffffffffu, mx1, 1));
        mx1 = fmaxf(mx1, __shfl_xor_sync(0xffffffffu, mx1, 2));
        const bool act0 = mx0 >= thr0, act1 = mx1 >= thr1;
        const int wact = __any_sync(0xffffffffu, act0 || act1);
        if (lane == 0) flags[wid] = wact;
        __syncthreads();
        int cact = 0;
#pragma unroll
        for (int w = 0; w < 8; w++) cact |= flags[w];

        if (cact) {
            const int j0 = j0base + t * 128;
#pragma unroll
            for (int it = 0; it < 16; it++) {
                int idx = it * 256 + tid;
                int r = idx >> 5, cq = (idx & 31) * 4;
                float4 f = *(const float4*)&g_v[(size_t)(j0 + r) * DV + cq];
                __nv_bfloat162 h0 = __floats2bfloat162_rn(f.x, f.y);
                __nv_bfloat162 h1 = __floats2bfloat162_rn(f.z, f.w);
                __nv_bfloat162 e0 = __floats2bfloat162_rn(f.x - __bfloat162float(h0.x),
                                                          f.y - __bfloat162float(h0.y));
                __nv_bfloat162 e1 = __floats2bfloat162_rn(f.z - __bfloat162float(h1.x),
                                                          f.w - __bfloat162float(h1.y));
                uint2 uh; uh.x = bf2_to_u32(h0); uh.y = bf2_to_u32(h1);
                uint2 ul; ul.x = bf2_to_u32(e0); ul.y = bf2_to_u32(e1);
                *(uint2*)(smem + AT_VH + r * ROWB + cq * 2) = uh;
                *(uint2*)(smem + AT_VL + r * ROWB + cq * 2) = ul;
            }
            __syncthreads();

            if (wact) {
#pragma unroll
                for (int s = 0; s < 8; s++) {
                    uint32_t pa[4];
                    float e00 = act0 ? __expf(sa[2 * s][0] - m0) : 0.f;
                    float e01 = act0 ? __expf(sa[2 * s][1] - m0) : 0.f;
                    float e10 = act1 ? __expf(sa[2 * s][2] - m1) : 0.f;
                    float e11 = act1 ? __expf(sa[2 * s][3] - m1) : 0.f;
                    float f00 = act0 ? __expf(sa[2 * s + 1][0] - m0) : 0.f;
                    float f01 = act0 ? __expf(sa[2 * s + 1][1] - m0) : 0.f;
                    float f10 = act1 ? __expf(sa[2 * s + 1][2] - m1) : 0.f;
                    float f11 = act1 ? __expf(sa[2 * s + 1][3] - m1) : 0.f;
                    __nv_bfloat162 b;
                    b = __floats2bfloat162_rn(e00, e01); pa[0] = bf2_to_u32(b);
                    l0 += __bfloat162float(b.x) + __bfloat162float(b.y);
                    b = __floats2bfloat162_rn(e10, e11); pa[1] = bf2_to_u32(b);
                    l1 += __bfloat162float(b.x) + __bfloat162float(b.y);
                    b = __floats2bfloat162_rn(f00, f01); pa[2] = bf2_to_u32(b);
                    l0 += __bfloat162float(b.x) + __bfloat162float(b.y);
                    b = __floats2bfloat162_rn(f10, f11); pa[3] = bf2_to_u32(b);
                    l1 += __bfloat162float(b.x) + __bfloat162float(b.y);

                    const uint32_t vrow = (uint32_t)(s * 16 + rA) * ROWB;
#pragma unroll
                    for (int nt = 0; nt < 16; nt++) {
                        uint32_t bh0, bh1;
                        LDSM_X2_T(bh0, bh1, sb + AT_VH + vrow + nt * 16);
                        MMA16816(oa[nt], pa, bh0, bh1);
                    }
#pragma unroll
                    for (int nt = 0; nt < 16; nt++) {
                        uint32_t bl0, bl1;
                        LDSM_X2_T(bl0, bl1, sb + AT_VL + vrow + nt * 16);
                        MMA16816(oa[nt], pa, bl0, bl1);
                    }
                }
            }
        }
    }

    l0 += __shfl_xor_sync(0xffffffffu, l0, 1);
    l0 += __shfl_xor_sync(0xffffffffu, l0, 2);
    l1 += __shfl_xor_sync(0xffffffffu, l1, 1);
    l1 += __shfl_xor_sync(0xffffffffu, l1, 2);
#pragma unroll
    for (int nt = 0; nt < 16; nt++) {
        const int col = nt * 8 + 2 * (lane & 3);
        float2 v0; v0.x = oa[nt][0]; v0.y = oa[nt][1];
        float2 v1; v1.x = oa[nt][2]; v1.y = oa[nt][3];
        *(float2*)&g_O[h][(size_t)rl * DV + col] = v0;
        *(float2*)&g_O[h][(size_t)rh * DV + col] = v1;
    }
    if ((lane & 3) == 0) {
        g_l[h][rl] = l0;
        g_l[h][rh] = l1;
    }
}

// ============================================================================
// combine v2: 4 float4/thread for MLP (grid 256)
// ============================================================================
__global__ __launch_bounds__(256, 4)
void combine_kernel(float* __restrict__ out) {
    const int base = blockIdx.x * 1024 + threadIdx.x;
#pragma unroll
    for (int j = 0; j < 4; j++) {
        const int i4 = base + j * 256;
        const int rowi = i4 >> 5;
        const float inv = 1.0f / (g_l[0][rowi] + g_l[1][rowi]);
        float4 a = ((const float4*)g_O[0])[i4];
        float4 b = ((const float4*)g_O[1])[i4];
        float4 o = make_float4((a.x + b.x) * inv, (a.y + b.y) * inv,
                               (a.z + b.z) * inv, (a.w + b.w) * inv);
        ((float4*)out)[i4] = o;
    }
}

// ---------------------------------------------------------------------------
extern "C" void kernel_launch(void* const* d_in, const int* in_sizes, int n_in,
                              void* d_out, int out_size) {
    const float* x   = (const float*)d_in[0];
    const float* Wqk = (const float*)d_in[1];
    const float* bqk = (const float*)d_in[2];
    const float* Wv  = (const float*)d_in[3];
    const float* bv  = (const float*)d_in[4];
    float* out = (float*)d_out;

    cudaFuncSetAttribute(proj_hmma_kernel, cudaFuncAttributeMaxDynamicSharedMemorySize, PJ_SMEM);
    cudaFuncSetAttribute(attn_kernel, cudaFuncAttributeMaxDynamicSharedMemorySize, ATT_SMEM);

    proj_hmma_kernel<<<dim3(NTOK / 128, 2), 256, PJ_SMEM>>>(x, Wqk, bqk, Wv, bv);
    attn_kernel<<<dim3(NTOK / 128, 2), 256, ATT_SMEM>>>();
    combine_kernel<<<256, 256>>>(out);
}